// round 13
// baseline (speedup 1.0000x reference)
#include <cuda_runtime.h>
#include <math.h>

// Problem constants (fixed by the reference: B=16, N=4096, C=21)
#define BB      16
#define NN      4096
#define CC      21
#define NBINS   1024
#define NCHUNK  64
#define CH      64                  // preds per chunk
#define CHP     (CH / 2)            // pairs per chunk
#define TSLICE  32                  // target slices per batch (main grid.y)
#define MTHR    128                 // main kernel threads (TSLICE*MTHR = NN)
#define NWRITER (BB * TSLICE)       // 512

// Scratch (device globals; rebuilt or reset every run)
__device__ ulonglong2 gA  [BB][NN / 2];   // {p0x,p1x},{p0y,p1y} bin-ordered pairs
__device__ ulonglong2 gBv [BB][NN / 2];   // {p0z,p1z},{nh0,nh1}
__device__ float4     g_tgt[BB][NN];      // bin-ordered targets (x,y,z,|t|^2)
__device__ float      g_tk [BB][NN];      // target projection keys
__device__ float2     g_cb [BB][NCHUNK];  // (suffix-min key, prefix-max key) per chunk
__device__ float4     g_ptmp[BB][NN];     // scatter temp for preds
__device__ float      g_pk [BB][NN];      // pred projection keys (bin order)
__device__ float      g_dirpart[BB * 2];  // non-sym direct-loss halves
__device__ float      g_part[NWRITER];    // per (batch,slice) loss partials
__device__ unsigned   g_done;             // writer counter (self-resetting)

typedef unsigned long long ull;

__device__ __forceinline__ ull fma2(ull a, ull b, ull c) {
    ull d;
    asm("fma.rn.f32x2 %0, %1, %2, %3;" : "=l"(d) : "l"(a), "l"(b), "l"(c));
    return d;
}
__device__ __forceinline__ ull pack2(float x) {
    ull d;
    asm("mov.b64 %0, {%1, %1};" : "=l"(d) : "r"(__float_as_uint(x)));
    return d;
}
__device__ __forceinline__ ull packab(float a, float b) {
    ull d;
    asm("mov.b64 %0, {%1, %2};" : "=l"(d) : "r"(__float_as_uint(a)), "r"(__float_as_uint(b)));
    return d;
}
__device__ __forceinline__ float lo2(ull v) { return __uint_as_float((unsigned)(v & 0xffffffffull)); }
__device__ __forceinline__ float hi2(ull v) { return __uint_as_float((unsigned)(v >> 32)); }

__device__ __forceinline__ unsigned atom_inc_acqrel(unsigned* p) {
    unsigned old;
    asm volatile("atom.acq_rel.gpu.global.add.u32 %0, [%1], %2;"
                 : "=r"(old) : "l"(p), "r"(1u) : "memory");
    return old;
}

// sym_flags layout sniff (bool array upcast by harness: int32 / float32 / uint8)
__device__ __forceinline__ int sniff_mode(const void* p) {
    const unsigned* w = (const unsigned*)p;
    bool is_i32 = true, is_f32 = true;
#pragma unroll
    for (int i = 0; i < CC; i++) {
        const unsigned v = w[i];
        if (v > 1u) is_i32 = false;
        if (v != 0u && v != 0x3F800000u) is_f32 = false;
    }
    return (is_i32 || is_f32) ? 0 : 1;
}
__device__ __forceinline__ bool read_flag(const void* p, int lb, int mode) {
    if (mode == 0) return ((const unsigned*)p)[lb] != 0u;
    return ((const unsigned char*)p)[lb] != 0;
}

// ============================================================================
// Kernel 1 (prep): grid (BB, 2), 1024 threads.
//  non-sym batch: each of the 2 blocks computes direct loss over half the pts.
//  sym batch:     which=0 bins PREDS by projection key and builds the packed
//                 pair arrays + conservative chunk bounds; which=1 bins
//                 TARGETS. Projection u = top singular direction of pred_r
//                 (power iteration; identical in both blocks).
// ============================================================================
__global__ void __launch_bounds__(1024)
prep_kernel(const float* __restrict__ pred_r,
            const float* __restrict__ gt_r,
            const float* __restrict__ points,
            const int*   __restrict__ labels,
            const void*  __restrict__ sym_flags) {
    __shared__ float skey[NN];        // 16KB
    __shared__ int   sh0[NBINS];
    __shared__ int   sh1[NBINS];
    __shared__ int   scur[NBINS];
    __shared__ float sredf[32];
    __shared__ float s_kmin, s_kmax;
    __shared__ float scmin[NCHUNK], scmax[NCHUNK];

    const int b = blockIdx.x, which = blockIdx.y, tid = threadIdx.x;
    const int mode = sniff_mode(sym_flags);
    const bool sym = read_flag(sym_flags, labels[b], mode);
    const float* P = points + (long)b * NN * 3;

    if (!sym) {
        // ---- direct loss over half the points ----
        float R[9], G[9];
#pragma unroll
        for (int i = 0; i < 9; i++) {
            R[i] = __ldg(pred_r + b * 9 + i);
            G[i] = __ldg(gt_r   + b * 9 + i);
        }
        float dsum = 0.0f;
#pragma unroll
        for (int k = 0; k < 2; k++) {
            const int n = which * 2048 + k * 1024 + tid;
            const float px = P[3 * n], py = P[3 * n + 1], pz = P[3 * n + 2];
            const float dx = fmaf(R[0] - G[0], px, fmaf(R[1] - G[1], py, (R[2] - G[2]) * pz));
            const float dy = fmaf(R[3] - G[3], px, fmaf(R[4] - G[4], py, (R[5] - G[5]) * pz));
            const float dz = fmaf(R[6] - G[6], px, fmaf(R[7] - G[7], py, (R[8] - G[8]) * pz));
            dsum += sqrtf(dx * dx + dy * dy + dz * dz);
        }
#pragma unroll
        for (int o = 16; o; o >>= 1) dsum += __shfl_down_sync(~0u, dsum, o);
        if ((tid & 31) == 0) sredf[tid >> 5] = dsum;
        __syncthreads();
        if (tid == 0) {
            float v = 0.0f;
            for (int w = 0; w < 32; w++) v += sredf[w];
            g_dirpart[b * 2 + which] = v;
        }
        return;
    }

    // ---- rotation matrices ----
    float R[9], M[9];
#pragma unroll
    for (int i = 0; i < 9; i++) R[i] = __ldg(pred_r + b * 9 + i);
    if (which == 0) {
#pragma unroll
        for (int i = 0; i < 9; i++) M[i] = R[i];
    } else {
#pragma unroll
        for (int i = 0; i < 9; i++) M[i] = __ldg(gt_r + b * 9 + i);
    }

    // ---- u = top eigenvector of R*R^T via power iteration (all threads identical)
    float A00 = R[0]*R[0]+R[1]*R[1]+R[2]*R[2];
    float A01 = R[0]*R[3]+R[1]*R[4]+R[2]*R[5];
    float A02 = R[0]*R[6]+R[1]*R[7]+R[2]*R[8];
    float A11 = R[3]*R[3]+R[4]*R[4]+R[5]*R[5];
    float A12 = R[3]*R[6]+R[4]*R[7]+R[5]*R[8];
    float A22 = R[6]*R[6]+R[7]*R[7]+R[8]*R[8];
    float vx = 1.0f, vy = 0.71f, vz = 0.41f;
#pragma unroll
    for (int it = 0; it < 16; it++) {
        const float nx = A00 * vx + A01 * vy + A02 * vz;
        const float ny = A01 * vx + A11 * vy + A12 * vz;
        const float nz = A02 * vx + A12 * vy + A22 * vz;
        const float inv = rsqrtf(nx * nx + ny * ny + nz * nz + 1e-30f);
        vx = nx * inv; vy = ny * inv; vz = nz * inv;
    }
    // w = M^T u  (key(x) = u . (M x) = w . x)
    const float wx = M[0] * vx + M[3] * vy + M[6] * vz;
    const float wy = M[1] * vx + M[4] * vy + M[7] * vz;
    const float wz = M[2] * vx + M[5] * vy + M[8] * vz;

    // ---- keys + min/max ----
    float kmn = 1e30f, kmx = -1e30f;
    for (int i = tid; i < NN; i += 1024) {
        const float k = wx * P[3 * i] + wy * P[3 * i + 1] + wz * P[3 * i + 2];
        skey[i] = k;
        kmn = fminf(kmn, k); kmx = fmaxf(kmx, k);
    }
    float v = kmn;
#pragma unroll
    for (int o = 16; o; o >>= 1) v = fminf(v, __shfl_down_sync(~0u, v, o));
    if ((tid & 31) == 0) sredf[tid >> 5] = v;
    __syncthreads();
    if (tid == 0) { float m = sredf[0]; for (int w = 1; w < 32; w++) m = fminf(m, sredf[w]); s_kmin = m; }
    __syncthreads();
    v = kmx;
#pragma unroll
    for (int o = 16; o; o >>= 1) v = fmaxf(v, __shfl_down_sync(~0u, v, o));
    if ((tid & 31) == 0) sredf[tid >> 5] = v;
    __syncthreads();
    if (tid == 0) { float m = sredf[0]; for (int w = 1; w < 32; w++) m = fmaxf(m, sredf[w]); s_kmax = m; }
    __syncthreads();
    const float kmin = s_kmin;
    const float scale = (float)NBINS / (s_kmax - kmin + 1e-12f);

    // ---- histogram ----
    sh0[tid] = 0;
    __syncthreads();
    for (int i = tid; i < NN; i += 1024) {
        int bin = (int)((skey[i] - kmin) * scale);
        bin = min(max(bin, 0), NBINS - 1);
        atomicAdd(&sh0[bin], 1);
    }
    __syncthreads();

    // ---- inclusive scan (ping-pong), then cursors = exclusive base ----
    const int cnt = sh0[tid];
    int* src = sh0; int* dst = sh1;
    for (int off = 1; off < NBINS; off <<= 1) {
        int x = src[tid];
        if (tid >= off) x += src[tid - off];
        dst[tid] = x;
        __syncthreads();
        int* t2 = src; src = dst; dst = t2;
    }
    scur[tid] = src[tid] - cnt;
    __syncthreads();

    // ---- scatter (bin-ordered) ----
    for (int i = tid; i < NN; i += 1024) {
        const float k = skey[i];
        int bin = (int)((k - kmin) * scale);
        bin = min(max(bin, 0), NBINS - 1);
        const int pos = atomicAdd(&scur[bin], 1);
        const float px = P[3 * i], py = P[3 * i + 1], pz = P[3 * i + 2];
        const float rx = fmaf(M[0], px, fmaf(M[1], py, M[2] * pz));
        const float ry = fmaf(M[3], px, fmaf(M[4], py, M[5] * pz));
        const float rz = fmaf(M[6], px, fmaf(M[7], py, M[8] * pz));
        const float nrm = rx * rx + ry * ry + rz * rz;
        if (which == 0) {
            g_ptmp[b][pos] = make_float4(rx, ry, rz, -0.5f * nrm);
            g_pk[b][pos] = k;
        } else {
            g_tgt[b][pos] = make_float4(rx, ry, rz, nrm);
            g_tk[b][pos] = k;
        }
    }
    __threadfence_block();   // make our global writes visible block-wide
    __syncthreads();

    if (which == 0) {
        // pack pairs for the FFMA2 inner loop
        for (int q = tid; q < NN / 2; q += 1024) {
            const float4 a = g_ptmp[b][2 * q];
            const float4 c = g_ptmp[b][2 * q + 1];
            ulonglong2 A2, B2;
            A2.x = packab(a.x, c.x); A2.y = packab(a.y, c.y);
            B2.x = packab(a.z, c.z); B2.y = packab(a.w, c.w);
            gA[b][q] = A2; gBv[b][q] = B2;
        }
        // conservative chunk bounds
        if (tid < NCHUNK) {
            float mn = 1e30f, mx = -1e30f;
            for (int j = 0; j < CH; j++) {
                const float k = g_pk[b][tid * CH + j];
                mn = fminf(mn, k); mx = fmaxf(mx, k);
            }
            scmin[tid] = mn; scmax[tid] = mx;
        }
        __syncthreads();
        if (tid == 0) {
            float s = 1e30f;
            for (int c = NCHUNK - 1; c >= 0; c--) { s = fminf(s, scmin[c]); scmin[c] = s; }
            float p = -1e30f;
            for (int c = 0; c < NCHUNK; c++) { p = fmaxf(p, scmax[c]); scmax[c] = p; }
            for (int c = 0; c < NCHUNK; c++) g_cb[b][c] = make_float2(scmin[c], scmax[c]);
        }
    }
}

// ============================================================================
// Kernel 2 (main): grid (BB, TSLICE), 128 threads. Pruned exact NN search.
// Each warp covers 32 consecutive bin-ordered targets; expands chunk-by-chunk
// outward from its home chunk, ballot-gated by the 1-Lipschitz projection
// bound. Non-sym blocks contribute part=0 (dir loss comes from prep).
// Last writer (counter) does the final 512 -> scalar reduction.
// ============================================================================
#define PROCESS_CHUNK(c)                                            \
    {                                                               \
        const ulonglong2* pA = &gA[b][(c) * CHP];                   \
        const ulonglong2* pB = &gBv[b][(c) * CHP];                  \
        _Pragma("unroll 8")                                         \
        for (int q = 0; q < CHP; q++) {                             \
            const ulonglong2 Aq = pA[q];                            \
            const ulonglong2 Bq = pB[q];                            \
            ull u = fma2(tz2, Bq.x, Bq.y);                          \
            u = fma2(ty2, Aq.y, u);                                 \
            u = fma2(tx2, Aq.x, u);                                 \
            best = fmaxf(best, fmaxf(lo2(u), hi2(u)));              \
        }                                                           \
    }

__global__ void __launch_bounds__(MTHR)
main_kernel(const float* __restrict__ mesh_diameter,
            const int*   __restrict__ labels,
            const void*  __restrict__ sym_flags,
            float*       __restrict__ out) {
    __shared__ float2 scb[NCHUNK];
    __shared__ float  red[MTHR / 32];
    __shared__ int    s_last;

    const int b = blockIdx.x, y = blockIdx.y, tid = threadIdx.x;
    const int mode = sniff_mode(sym_flags);
    const bool sym = read_flag(sym_flags, labels[b], mode);

    float part = 0.0f;
    if (sym) {
        if (tid < NCHUNK) scb[tid] = g_cb[b][tid];
        __syncthreads();

        const int n = y * MTHR + tid;
        const float4 t = g_tgt[b][n];
        const float kt = g_tk[b][n];
        const ull tx2 = pack2(t.x), ty2 = pack2(t.y), tz2 = pack2(t.z);
        const float tn = t.w;
        float best = -1e30f;

        // home chunk: largest c with suffix-min-key <= median lane's key
        const float ktm = __shfl_sync(~0u, kt, 16);
        int c0 = 0;
#pragma unroll
        for (int st = 32; st; st >>= 1) {
            const int c = c0 + st;
            if (c < NCHUNK && scb[c].x <= ktm) c0 = c;
        }
        PROCESS_CHUNK(c0);

        int hi = c0 + 1, lo = c0 - 1;
        bool dh = (hi >= NCHUNK), dl = (lo < 0);
        while (!dh || !dl) {
            if (!dh) {
                const float dz = fmaxf(scb[hi].x - kt, 0.0f);
                const float d2b = fmaf(-2.0f, best, tn) * 1.0001f + 1e-12f;
                const bool want = dz * dz < d2b;
                if (__ballot_sync(~0u, want)) { PROCESS_CHUNK(hi); hi++; dh = (hi >= NCHUNK); }
                else dh = true;
            }
            if (!dl) {
                const float dz = fmaxf(kt - scb[lo].y, 0.0f);
                const float d2b = fmaf(-2.0f, best, tn) * 1.0001f + 1e-12f;
                const bool want = dz * dz < d2b;
                if (__ballot_sync(~0u, want)) { PROCESS_CHUNK(lo); lo--; dl = (lo < 0); }
                else dl = true;
            }
        }
        part = sqrtf(fmaxf(fmaf(-2.0f, best, tn), 0.0f));
    }

    // ---- block reduction -> g_part[slice] ----
#pragma unroll
    for (int o = 16; o; o >>= 1) part += __shfl_down_sync(~0u, part, o);
    if ((tid & 31) == 0) red[tid >> 5] = part;
    __syncthreads();
    if (tid == 0) {
        float v = 0.0f;
#pragma unroll
        for (int w = 0; w < MTHR / 32; w++) v += red[w];
        g_part[b * TSLICE + y] = v;
        const unsigned old = atom_inc_acqrel(&g_done);
        s_last = (old == (unsigned)(NWRITER - 1)) ? 1 : 0;
    }
    __syncthreads();

    // ---- last writer: final reduction ----
    if (s_last) {
        if (tid < 32) {
            float v = 0.0f;
            if (tid < BB) {
                const int lb = labels[tid];
                float sum = 0.0f;
                if (read_flag(sym_flags, lb, mode)) {
#pragma unroll
                    for (int s = 0; s < TSLICE; s++) sum += g_part[tid * TSLICE + s];
                } else {
                    sum = g_dirpart[tid * 2] + g_dirpart[tid * 2 + 1];
                }
                v = sum * (1.0f / NN) / __ldg(mesh_diameter + lb);
            }
#pragma unroll
            for (int o = 16; o; o >>= 1) v += __shfl_down_sync(~0u, v, o);
            if (tid == 0) {
                *out = v * (1.0f / BB);
                g_done = 0;   // reset for next graph replay (deterministic)
            }
        }
    }
}

// ============================================================================
extern "C" void kernel_launch(void* const* d_in, const int* in_sizes, int n_in,
                              void* d_out, int out_size) {
    const float* pred_r        = (const float*)d_in[0];
    const float* gt_r          = (const float*)d_in[1];
    const float* points        = (const float*)d_in[2];
    const float* mesh_diameter = (const float*)d_in[3];
    const int*   labels        = (const int*)d_in[4];
    const void*  sym_flags     = d_in[5];

    prep_kernel<<<dim3(BB, 2), 1024>>>(pred_r, gt_r, points, labels, sym_flags);
    main_kernel<<<dim3(BB, TSLICE), MTHR>>>(mesh_diameter, labels, sym_flags, (float*)d_out);
}

// round 14
// speedup vs baseline: 2.2901x; 2.2901x over previous
#include <cuda_runtime.h>
#include <math.h>

// Problem constants (fixed by the reference: B=16, N=4096, C=21)
#define BB      16
#define NN      4096
#define CC      21
#define NBINS   1024
#define NCHUNK  64
#define CH      64                  // preds per chunk
#define CHP     (CH / 2)            // 32 pairs per chunk
#define TILE_CH 8                   // chunks staged per smem tile (256 pairs, 8KB)
#define TSLICE  16                  // target slices per batch (main grid.y)
#define MTHR    128                 // main kernel threads; 2 targets/thread
#define NWRITER (BB * TSLICE)       // 256

// Scratch (device globals; rebuilt every run)
__device__ ulonglong2 gA  [BB][NN / 2];   // {p0x,p1x},{p0y,p1y} bin-ordered pairs
__device__ ulonglong2 gBv [BB][NN / 2];   // {p0z,p1z},{nh0,nh1}
__device__ float4     g_tgt[BB][NN];      // bin-ordered targets (x,y,z,|t|^2)
__device__ float      g_tk [BB][NN];      // target projection keys
__device__ float2     g_cb [BB][NCHUNK];  // RAW per-chunk (min key, max key)
__device__ float4     g_ptmp[BB][NN];     // scatter temp for preds
__device__ float      g_pk [BB][NN];      // pred projection keys (bin order)
__device__ float      g_dirpart[BB * 2];  // non-sym direct-loss halves
__device__ float      g_part[NWRITER];    // per (batch,slice) loss partials
__device__ unsigned   g_done;             // writer counter (self-resetting)

typedef unsigned long long ull;

__device__ __forceinline__ ull fma2(ull a, ull b, ull c) {
    ull d;
    asm("fma.rn.f32x2 %0, %1, %2, %3;" : "=l"(d) : "l"(a), "l"(b), "l"(c));
    return d;
}
__device__ __forceinline__ ull pack2(float x) {
    ull d;
    asm("mov.b64 %0, {%1, %1};" : "=l"(d) : "r"(__float_as_uint(x)));
    return d;
}
__device__ __forceinline__ ull packab(float a, float b) {
    ull d;
    asm("mov.b64 %0, {%1, %2};" : "=l"(d) : "r"(__float_as_uint(a)), "r"(__float_as_uint(b)));
    return d;
}
__device__ __forceinline__ float lo2(ull v) { return __uint_as_float((unsigned)(v & 0xffffffffull)); }
__device__ __forceinline__ float hi2(ull v) { return __uint_as_float((unsigned)(v >> 32)); }

__device__ __forceinline__ unsigned atom_inc_acqrel(unsigned* p) {
    unsigned old;
    asm volatile("atom.acq_rel.gpu.global.add.u32 %0, [%1], %2;"
                 : "=r"(old) : "l"(p), "r"(1u) : "memory");
    return old;
}

// sym_flags layout sniff (bool array upcast by harness: int32 / float32 / uint8)
__device__ __forceinline__ int sniff_mode(const void* p) {
    const unsigned* w = (const unsigned*)p;
    bool is_i32 = true, is_f32 = true;
#pragma unroll
    for (int i = 0; i < CC; i++) {
        const unsigned v = w[i];
        if (v > 1u) is_i32 = false;
        if (v != 0u && v != 0x3F800000u) is_f32 = false;
    }
    return (is_i32 || is_f32) ? 0 : 1;
}
__device__ __forceinline__ bool read_flag(const void* p, int lb, int mode) {
    if (mode == 0) return ((const unsigned*)p)[lb] != 0u;
    return ((const unsigned char*)p)[lb] != 0;
}

// ============================================================================
// Kernel 1 (prep): grid (BB, 2), 1024 threads. (Correctness-proven in R13,
// minus the suffix/prefix transform: g_cb now stores RAW chunk min/max.)
// ============================================================================
__global__ void __launch_bounds__(1024)
prep_kernel(const float* __restrict__ pred_r,
            const float* __restrict__ gt_r,
            const float* __restrict__ points,
            const int*   __restrict__ labels,
            const void*  __restrict__ sym_flags) {
    __shared__ float skey[NN];
    __shared__ int   sh0[NBINS];
    __shared__ int   sh1[NBINS];
    __shared__ int   scur[NBINS];
    __shared__ float sredf[32];
    __shared__ float s_kmin, s_kmax;

    const int b = blockIdx.x, which = blockIdx.y, tid = threadIdx.x;
    const int mode = sniff_mode(sym_flags);
    const bool sym = read_flag(sym_flags, labels[b], mode);
    const float* P = points + (long)b * NN * 3;

    if (!sym) {
        float R[9], G[9];
#pragma unroll
        for (int i = 0; i < 9; i++) {
            R[i] = __ldg(pred_r + b * 9 + i);
            G[i] = __ldg(gt_r   + b * 9 + i);
        }
        float dsum = 0.0f;
#pragma unroll
        for (int k = 0; k < 2; k++) {
            const int n = which * 2048 + k * 1024 + tid;
            const float px = P[3 * n], py = P[3 * n + 1], pz = P[3 * n + 2];
            const float dx = fmaf(R[0] - G[0], px, fmaf(R[1] - G[1], py, (R[2] - G[2]) * pz));
            const float dy = fmaf(R[3] - G[3], px, fmaf(R[4] - G[4], py, (R[5] - G[5]) * pz));
            const float dz = fmaf(R[6] - G[6], px, fmaf(R[7] - G[7], py, (R[8] - G[8]) * pz));
            dsum += sqrtf(dx * dx + dy * dy + dz * dz);
        }
#pragma unroll
        for (int o = 16; o; o >>= 1) dsum += __shfl_down_sync(~0u, dsum, o);
        if ((tid & 31) == 0) sredf[tid >> 5] = dsum;
        __syncthreads();
        if (tid == 0) {
            float v = 0.0f;
            for (int w = 0; w < 32; w++) v += sredf[w];
            g_dirpart[b * 2 + which] = v;
        }
        return;
    }

    float R[9], M[9];
#pragma unroll
    for (int i = 0; i < 9; i++) R[i] = __ldg(pred_r + b * 9 + i);
    if (which == 0) {
#pragma unroll
        for (int i = 0; i < 9; i++) M[i] = R[i];
    } else {
#pragma unroll
        for (int i = 0; i < 9; i++) M[i] = __ldg(gt_r + b * 9 + i);
    }

    // top eigenvector of R R^T (power iteration; identical across threads/blocks)
    float A00 = R[0]*R[0]+R[1]*R[1]+R[2]*R[2];
    float A01 = R[0]*R[3]+R[1]*R[4]+R[2]*R[5];
    float A02 = R[0]*R[6]+R[1]*R[7]+R[2]*R[8];
    float A11 = R[3]*R[3]+R[4]*R[4]+R[5]*R[5];
    float A12 = R[3]*R[6]+R[4]*R[7]+R[5]*R[8];
    float A22 = R[6]*R[6]+R[7]*R[7]+R[8]*R[8];
    float vx = 1.0f, vy = 0.71f, vz = 0.41f;
#pragma unroll
    for (int it = 0; it < 16; it++) {
        const float nx = A00 * vx + A01 * vy + A02 * vz;
        const float ny = A01 * vx + A11 * vy + A12 * vz;
        const float nz = A02 * vx + A12 * vy + A22 * vz;
        const float inv = rsqrtf(nx * nx + ny * ny + nz * nz + 1e-30f);
        vx = nx * inv; vy = ny * inv; vz = nz * inv;
    }
    const float wx = M[0] * vx + M[3] * vy + M[6] * vz;
    const float wy = M[1] * vx + M[4] * vy + M[7] * vz;
    const float wz = M[2] * vx + M[5] * vy + M[8] * vz;

    float kmn = 1e30f, kmx = -1e30f;
    for (int i = tid; i < NN; i += 1024) {
        const float k = wx * P[3 * i] + wy * P[3 * i + 1] + wz * P[3 * i + 2];
        skey[i] = k;
        kmn = fminf(kmn, k); kmx = fmaxf(kmx, k);
    }
    float v = kmn;
#pragma unroll
    for (int o = 16; o; o >>= 1) v = fminf(v, __shfl_down_sync(~0u, v, o));
    if ((tid & 31) == 0) sredf[tid >> 5] = v;
    __syncthreads();
    if (tid == 0) { float m = sredf[0]; for (int w = 1; w < 32; w++) m = fminf(m, sredf[w]); s_kmin = m; }
    __syncthreads();
    v = kmx;
#pragma unroll
    for (int o = 16; o; o >>= 1) v = fmaxf(v, __shfl_down_sync(~0u, v, o));
    if ((tid & 31) == 0) sredf[tid >> 5] = v;
    __syncthreads();
    if (tid == 0) { float m = sredf[0]; for (int w = 1; w < 32; w++) m = fmaxf(m, sredf[w]); s_kmax = m; }
    __syncthreads();
    const float kmin = s_kmin;
    const float scale = (float)NBINS / (s_kmax - kmin + 1e-12f);

    sh0[tid] = 0;
    __syncthreads();
    for (int i = tid; i < NN; i += 1024) {
        int bin = (int)((skey[i] - kmin) * scale);
        bin = min(max(bin, 0), NBINS - 1);
        atomicAdd(&sh0[bin], 1);
    }
    __syncthreads();

    const int cnt = sh0[tid];
    int* src = sh0; int* dst = sh1;
    for (int off = 1; off < NBINS; off <<= 1) {
        int x = src[tid];
        if (tid >= off) x += src[tid - off];
        dst[tid] = x;
        __syncthreads();
        int* t2 = src; src = dst; dst = t2;
    }
    scur[tid] = src[tid] - cnt;
    __syncthreads();

    for (int i = tid; i < NN; i += 1024) {
        const float k = skey[i];
        int bin = (int)((k - kmin) * scale);
        bin = min(max(bin, 0), NBINS - 1);
        const int pos = atomicAdd(&scur[bin], 1);
        const float px = P[3 * i], py = P[3 * i + 1], pz = P[3 * i + 2];
        const float rx = fmaf(M[0], px, fmaf(M[1], py, M[2] * pz));
        const float ry = fmaf(M[3], px, fmaf(M[4], py, M[5] * pz));
        const float rz = fmaf(M[6], px, fmaf(M[7], py, M[8] * pz));
        const float nrm = rx * rx + ry * ry + rz * rz;
        if (which == 0) {
            g_ptmp[b][pos] = make_float4(rx, ry, rz, -0.5f * nrm);
            g_pk[b][pos] = k;
        } else {
            g_tgt[b][pos] = make_float4(rx, ry, rz, nrm);
            g_tk[b][pos] = k;
        }
    }
    __threadfence_block();
    __syncthreads();

    if (which == 0) {
        for (int q = tid; q < NN / 2; q += 1024) {
            const float4 a = g_ptmp[b][2 * q];
            const float4 c = g_ptmp[b][2 * q + 1];
            ulonglong2 A2, B2;
            A2.x = packab(a.x, c.x); A2.y = packab(a.y, c.y);
            B2.x = packab(a.z, c.z); B2.y = packab(a.w, c.w);
            gA[b][q] = A2; gBv[b][q] = B2;
        }
        if (tid < NCHUNK) {
            float mn = 1e30f, mx = -1e30f;
            for (int j = 0; j < CH; j++) {
                const float k = g_pk[b][tid * CH + j];
                mn = fminf(mn, k); mx = fmaxf(mx, k);
            }
            g_cb[b][tid] = make_float2(mn, mx);   // RAW bounds
        }
    }
}

// ============================================================================
// Kernel 2 (main): grid (BB, TSLICE), 128 threads, 2 targets/thread.
// Two-phase block-uniform pruned scan, smem-staged tiles of <=8 chunks.
// ============================================================================
__global__ void __launch_bounds__(MTHR)
main_kernel(const float* __restrict__ mesh_diameter,
            const int*   __restrict__ labels,
            const void*  __restrict__ sym_flags,
            float*       __restrict__ out) {
    __shared__ float2     scb[NCHUNK];
    __shared__ ulonglong2 sA[TILE_CH * CHP];   // 4KB
    __shared__ ulonglong2 sB[TILE_CH * CHP];   // 4KB
    __shared__ int        slist[NCHUNK];
    __shared__ char       sdone[NCHUNK];
    __shared__ int        s_cnt, s_last;
    __shared__ float      sredf[MTHR / 32], sredf2[MTHR / 32];
    __shared__ float      s_A, s_B, s_r;

    const int b = blockIdx.x, y = blockIdx.y, tid = threadIdx.x;
    const int mode = sniff_mode(sym_flags);
    const bool sym = read_flag(sym_flags, labels[b], mode);

    float part = 0.0f;
    if (sym) {
        if (tid < NCHUNK) { scb[tid] = g_cb[b][tid]; sdone[tid] = 0; }

        const int n0 = y * 256 + tid;
        const int n1 = n0 + 128;
        const float4 t0 = g_tgt[b][n0];
        const float4 t1 = g_tgt[b][n1];
        const float  kt0 = g_tk[b][n0], kt1 = g_tk[b][n1];
        const ull tx0 = pack2(t0.x), ty0 = pack2(t0.y), tz0 = pack2(t0.z);
        const ull tx1 = pack2(t1.x), ty1 = pack2(t1.y), tz1 = pack2(t1.z);
        float best0 = -1e30f, best1 = -1e30f;

        // block key range [A, B]
        float mn = fminf(kt0, kt1), mx = fmaxf(kt0, kt1);
#pragma unroll
        for (int o = 16; o; o >>= 1) {
            mn = fminf(mn, __shfl_down_sync(~0u, mn, o));
            mx = fmaxf(mx, __shfl_down_sync(~0u, mx, o));
        }
        if ((tid & 31) == 0) { sredf[tid >> 5] = mn; sredf2[tid >> 5] = mx; }
        __syncthreads();
        if (tid == 0) {
            float a = sredf[0], c = sredf2[0];
            for (int w = 1; w < MTHR / 32; w++) { a = fminf(a, sredf[w]); c = fmaxf(c, sredf2[w]); }
            s_A = a; s_B = c;
        }
        __syncthreads();
        const float A = s_A, B = s_B;

        for (int phase = 0; phase < 2; phase++) {
            // ---- build chunk list (thread 0; 64 iterations, block-uniform) ----
            if (tid == 0) {
                int c2 = 0;
                if (phase == 0) {
                    for (int c = 0; c < NCHUNK; c++)
                        if (scb[c].y >= A && scb[c].x <= B) { slist[c2++] = c; sdone[c] = 1; }
                    if (c2 == 0) {   // targets' keys outside pred range: take nearest chunk
                        const float mid = 0.5f * (A + B);
                        int bc = 0; float bd = 1e30f;
                        for (int c = 0; c < NCHUNK; c++) {
                            const float d = fminf(fabsf(scb[c].x - mid), fabsf(scb[c].y - mid));
                            if (d < bd) { bd = d; bc = c; }
                        }
                        slist[c2++] = bc; sdone[bc] = 1;
                    }
                } else {
                    const float r = s_r;
                    for (int c = 0; c < NCHUNK; c++)
                        if (!sdone[c] && scb[c].y >= A - r && scb[c].x <= B + r) { slist[c2++] = c; sdone[c] = 1; }
                }
                s_cnt = c2;
            }
            __syncthreads();
            const int cnt = s_cnt;

            // ---- process list in tiles of <= TILE_CH chunks ----
            for (int base = 0; base < cnt; base += TILE_CH) {
                const int m = min(TILE_CH, cnt - base);
                const int npair = m * CHP;
                for (int idx = tid; idx < npair; idx += MTHR) {
                    const int c = slist[base + (idx >> 5)];   // CHP == 32
                    const int q = idx & 31;
                    sA[idx] = gA[b][c * CHP + q];
                    sB[idx] = gBv[b][c * CHP + q];
                }
                __syncthreads();
#pragma unroll 4
                for (int q = 0; q < npair; q++) {
                    const ulonglong2 Aq = sA[q];
                    const ulonglong2 Bq = sB[q];
                    ull u0 = fma2(tz0, Bq.x, Bq.y);
                    u0 = fma2(ty0, Aq.y, u0);
                    u0 = fma2(tx0, Aq.x, u0);
                    ull u1 = fma2(tz1, Bq.x, Bq.y);
                    u1 = fma2(ty1, Aq.y, u1);
                    u1 = fma2(tx1, Aq.x, u1);
                    best0 = fmaxf(best0, fmaxf(lo2(u0), hi2(u0)));
                    best1 = fmaxf(best1, fmaxf(lo2(u1), hi2(u1)));
                }
                __syncthreads();
            }

            // ---- after phase 0: r_max = block max NN-distance bound ----
            if (phase == 0) {
                const float d0 = sqrtf(fmaxf(fmaf(-2.0f, best0, t0.w), 0.0f));
                const float d1 = sqrtf(fmaxf(fmaf(-2.0f, best1, t1.w), 0.0f));
                float rm = fmaxf(d0, d1);
#pragma unroll
                for (int o = 16; o; o >>= 1) rm = fmaxf(rm, __shfl_down_sync(~0u, rm, o));
                if ((tid & 31) == 0) sredf[tid >> 5] = rm;
                __syncthreads();
                if (tid == 0) {
                    float r = sredf[0];
                    for (int w = 1; w < MTHR / 32; w++) r = fmaxf(r, sredf[w]);
                    s_r = r * 1.0001f + 1e-3f;   // conservative slack
                }
                __syncthreads();
            }
        }

        part = sqrtf(fmaxf(fmaf(-2.0f, best0, t0.w), 0.0f))
             + sqrtf(fmaxf(fmaf(-2.0f, best1, t1.w), 0.0f));
    }

    // ---- block reduction -> g_part[slice] ----
#pragma unroll
    for (int o = 16; o; o >>= 1) part += __shfl_down_sync(~0u, part, o);
    if ((tid & 31) == 0) sredf[tid >> 5] = part;
    __syncthreads();
    if (tid == 0) {
        float v = 0.0f;
#pragma unroll
        for (int w = 0; w < MTHR / 32; w++) v += sredf[w];
        g_part[b * TSLICE + y] = v;
        const unsigned old = atom_inc_acqrel(&g_done);
        s_last = (old == (unsigned)(NWRITER - 1)) ? 1 : 0;
    }
    __syncthreads();

    if (s_last) {
        if (tid < 32) {
            float v = 0.0f;
            if (tid < BB) {
                const int lb = labels[tid];
                float sum = 0.0f;
                if (read_flag(sym_flags, lb, mode)) {
#pragma unroll
                    for (int s = 0; s < TSLICE; s++) sum += g_part[tid * TSLICE + s];
                } else {
                    sum = g_dirpart[tid * 2] + g_dirpart[tid * 2 + 1];
                }
                v = sum * (1.0f / NN) / __ldg(mesh_diameter + lb);
            }
#pragma unroll
            for (int o = 16; o; o >>= 1) v += __shfl_down_sync(~0u, v, o);
            if (tid == 0) {
                *out = v * (1.0f / BB);
                g_done = 0;
            }
        }
    }
}

// ============================================================================
extern "C" void kernel_launch(void* const* d_in, const int* in_sizes, int n_in,
                              void* d_out, int out_size) {
    const float* pred_r        = (const float*)d_in[0];
    const float* gt_r          = (const float*)d_in[1];
    const float* points        = (const float*)d_in[2];
    const float* mesh_diameter = (const float*)d_in[3];
    const int*   labels        = (const int*)d_in[4];
    const void*  sym_flags     = d_in[5];

    prep_kernel<<<dim3(BB, 2), 1024>>>(pred_r, gt_r, points, labels, sym_flags);
    main_kernel<<<dim3(BB, TSLICE), MTHR>>>(mesh_diameter, labels, sym_flags, (float*)d_out);
}

// round 15
// speedup vs baseline: 8.1078x; 3.5404x over previous
#include <cuda_runtime.h>
#include <math.h>

// Problem constants (fixed by the reference: B=16, N=4096, C=21)
#define BB      16
#define NN      4096
#define CC      21
#define SLICES  8                   // target slices per batch (grid.y), 512 targets each
#define PSPLIT  32                  // pred chunks per batch (grid.z)
#define PPTS    (NN / PSPLIT)       // 128 pred points per chunk
#define CPAIR   (PPTS / 2)          // 64 pred pairs per chunk (2 KB smem)
#define NTHR    128
#define NWRITER (BB * SLICES)       // 128

// Scratch (device globals; zero-initialized; every entry reset each run)
__device__ unsigned g_best[BB * NN];   // monotonic-encoded running max scores
__device__ float    g_part[NWRITER];   // per (batch,slice) loss partials
__device__ unsigned g_cnt [NWRITER];   // per-slice sibling counters
__device__ unsigned g_done;            // global writer counter

typedef unsigned long long ull;

// ---- packed f32x2 helpers (sm_100+) ----
__device__ __forceinline__ ull fma2(ull a, ull b, ull c) {
    ull d;
    asm("fma.rn.f32x2 %0, %1, %2, %3;" : "=l"(d) : "l"(a), "l"(b), "l"(c));
    return d;
}
__device__ __forceinline__ ull pack2(float x) {
    ull d;
    asm("mov.b64 %0, {%1, %1};" : "=l"(d) : "r"(__float_as_uint(x)));
    return d;
}
__device__ __forceinline__ ull packab(float a, float b) {
    ull d;
    asm("mov.b64 %0, {%1, %2};" : "=l"(d) : "r"(__float_as_uint(a)), "r"(__float_as_uint(b)));
    return d;
}
__device__ __forceinline__ float lo2(ull v) { return __uint_as_float((unsigned)(v & 0xffffffffull)); }
__device__ __forceinline__ float hi2(ull v) { return __uint_as_float((unsigned)(v >> 32)); }

// order-preserving float <-> uint (zero encodes below every finite value's code)
__device__ __forceinline__ unsigned enc_f(float f) {
    const unsigned b = __float_as_uint(f);
    return (b & 0x80000000u) ? ~b : (b | 0x80000000u);
}
__device__ __forceinline__ float dec_f(unsigned u) {
    const unsigned b = (u & 0x80000000u) ? (u ^ 0x80000000u) : ~u;
    return __uint_as_float(b);
}

__device__ __forceinline__ unsigned atom_inc_acqrel(unsigned* p) {
    unsigned old;
    asm volatile("atom.acq_rel.gpu.global.add.u32 %0, [%1], %2;"
                 : "=r"(old) : "l"(p), "r"(1u) : "memory");
    return old;
}
__device__ __forceinline__ void red_max_u32(unsigned* p, unsigned v) {
    asm volatile("red.global.max.u32 [%0], %1;" :: "l"(p), "r"(v) : "memory");
}

// sym_flags layout sniff (bool array upcast by harness: int32 / float32 / uint8)
__device__ __forceinline__ int sniff_mode(const void* p) {
    const unsigned* w = (const unsigned*)p;
    bool is_i32 = true, is_f32 = true;
#pragma unroll
    for (int i = 0; i < CC; i++) {
        const unsigned v = w[i];
        if (v > 1u) is_i32 = false;
        if (v != 0u && v != 0x3F800000u) is_f32 = false;
    }
    return (is_i32 || is_f32) ? 0 : 1;
}
__device__ __forceinline__ bool read_flag(const void* p, int lb, int mode) {
    if (mode == 0) return ((const unsigned*)p)[lb] != 0u;
    return ((const unsigned char*)p)[lb] != 0;
}

// ============================================================================
// ONE kernel. grid (BB, SLICES, PSPLIT) = 4096 blocks, 128 threads, 2KB smem.
// R11 machinery; inner body now covers 4 targets per thread (high ILP) at
// high block count (PSPLIT=32) so warps/SM stay ~40 under the register cap.
//  sym batch:   block scans pred chunk z (128 rotated preds in smem) for its
//               512 targets (4/thread); red.max publishes encoded scores into
//               g_best. Last of 32 siblings combines, sqrts, writes slice
//               partial, resets its g_best entries.
//  non-sym:     z==0 block computes the direct loss for its 512-pt slice.
//  last writer reduces 128 partials -> scalar loss, resets.
// ============================================================================
__global__ void __launch_bounds__(NTHR, 8)
fused_kernel(const float* __restrict__ pred_r,
             const float* __restrict__ gt_r,
             const float* __restrict__ points,
             const float* __restrict__ mesh_diameter,
             const int*   __restrict__ labels,
             const void*  __restrict__ sym_flags,
             float*       __restrict__ out) {
    __shared__ ulonglong2 smA[CPAIR];    // {p0x,p1x} , {p0y,p1y}
    __shared__ ulonglong2 smB[CPAIR];    // {p0z,p1z} , {nh0,nh1}
    __shared__ float red[NTHR / 32];
    __shared__ int   s_sym, s_combine, s_last;

    const int b     = blockIdx.x;
    const int y     = blockIdx.y;
    const int z     = blockIdx.z;
    const int tid   = threadIdx.x;
    const int slice = b * SLICES + y;

    if (tid == 0) {
        const int m = sniff_mode(sym_flags);
        s_sym = read_flag(sym_flags, labels[b], m) ? 1 : 0;
    }
    __syncthreads();

    float part  = 0.0f;
    bool  wrote_part = false;

    if (s_sym) {
        float R[9], G[9];
#pragma unroll
        for (int i = 0; i < 9; i++) {
            R[i] = __ldg(pred_r + b * 9 + i);
            G[i] = __ldg(gt_r   + b * 9 + i);
        }

        // ---- own 4 targets rotated by gt_r ----
        float tw[4]; ull txp[4], typ[4], tzp[4];
#pragma unroll
        for (int k = 0; k < 4; k++) {
            const int n = y * 512 + k * 128 + tid;
            const float* p = points + ((long)b * NN + n) * 3;
            const float px = p[0], py = p[1], pz = p[2];
            const float tx = fmaf(G[0], px, fmaf(G[1], py, G[2] * pz));
            const float ty = fmaf(G[3], px, fmaf(G[4], py, G[5] * pz));
            const float tz = fmaf(G[6], px, fmaf(G[7], py, G[8] * pz));
            tw[k]  = tx * tx + ty * ty + tz * tz;
            txp[k] = pack2(tx); typ[k] = pack2(ty); tzp[k] = pack2(tz);
        }

        // ---- fill: rotate this chunk's 128 preds into interleaved smem ----
        if (tid < CPAIR) {
            const float2* pts2 = (const float2*)(points + ((long)b * NN + z * PPTS) * 3);
            const int q = tid;
            const float2 f0 = pts2[3 * q + 0];   // p0x p0y
            const float2 f1 = pts2[3 * q + 1];   // p0z p1x
            const float2 f2 = pts2[3 * q + 2];   // p1y p1z

            const float ax = fmaf(R[0], f0.x, fmaf(R[1], f0.y, R[2] * f1.x));
            const float ay = fmaf(R[3], f0.x, fmaf(R[4], f0.y, R[5] * f1.x));
            const float az = fmaf(R[6], f0.x, fmaf(R[7], f0.y, R[8] * f1.x));
            const float bx = fmaf(R[0], f1.y, fmaf(R[1], f2.x, R[2] * f2.y));
            const float by = fmaf(R[3], f1.y, fmaf(R[4], f2.x, R[5] * f2.y));
            const float bz = fmaf(R[6], f1.y, fmaf(R[7], f2.x, R[8] * f2.y));
            const float na = -0.5f * (ax * ax + ay * ay + az * az);
            const float nb = -0.5f * (bx * bx + by * by + bz * bz);

            ulonglong2 A, Bv;
            A.x  = packab(ax, bx);
            A.y  = packab(ay, by);
            Bv.x = packab(az, bz);
            Bv.y = packab(na, nb);
            smA[q] = A;
            smB[q] = Bv;
        }
        __syncthreads();

        // ---- inner loop: max score over 64 pred pairs, 4 targets ----
        float best[4] = {-1e30f, -1e30f, -1e30f, -1e30f};
#pragma unroll 8
        for (int q = 0; q < CPAIR; q++) {
            const ulonglong2 A  = smA[q];
            const ulonglong2 Bv = smB[q];
#pragma unroll
            for (int k = 0; k < 4; k++) {
                ull u = fma2(tzp[k], Bv.x, Bv.y);
                u = fma2(typ[k], A.y, u);
                u = fma2(txp[k], A.x, u);
                best[k] = fmaxf(best[k], fmaxf(lo2(u), hi2(u)));
            }
        }

        // ---- publish via red.max; last sibling combines ----
#pragma unroll
        for (int k = 0; k < 4; k++)
            red_max_u32(&g_best[b * NN + y * 512 + k * 128 + tid], enc_f(best[k]));
        if (tid == 0) {
            const unsigned old = atom_inc_acqrel(&g_cnt[slice]);
            s_combine = (old == PSPLIT - 1) ? 1 : 0;
        }
        __syncthreads();

        if (s_combine) {
#pragma unroll
            for (int k = 0; k < 4; k++) {
                const int idx = b * NN + y * 512 + k * 128 + tid;
                const unsigned u = g_best[idx];
                part += sqrtf(fmaxf(fmaf(-2.0f, dec_f(u), tw[k]), 0.0f));
                g_best[idx] = 0u;   // reset for next graph replay
            }
            if (tid == 0) g_cnt[slice] = 0;
            wrote_part = true;
        }
    } else {
        if (z != 0) return;     // only one sibling does the direct loss
        float R[9], G[9];
#pragma unroll
        for (int i = 0; i < 9; i++) {
            R[i] = __ldg(pred_r + b * 9 + i);
            G[i] = __ldg(gt_r   + b * 9 + i);
        }
#pragma unroll
        for (int k = 0; k < 4; k++) {
            const int n = y * 512 + k * 128 + tid;
            const float* p = points + ((long)b * NN + n) * 3;
            const float px = p[0], py = p[1], pz = p[2];
            const float dx = fmaf(R[0] - G[0], px, fmaf(R[1] - G[1], py, (R[2] - G[2]) * pz));
            const float dy = fmaf(R[3] - G[3], px, fmaf(R[4] - G[4], py, (R[5] - G[5]) * pz));
            const float dz = fmaf(R[6] - G[6], px, fmaf(R[7] - G[7], py, (R[8] - G[8]) * pz));
            part += sqrtf(dx * dx + dy * dy + dz * dz);
        }
        wrote_part = true;
    }

    if (!wrote_part) return;

    // ---- block reduction of part (128 threads) -> g_part[slice] ----
#pragma unroll
    for (int o = 16; o > 0; o >>= 1) part += __shfl_down_sync(0xffffffffu, part, o);
    if ((tid & 31) == 0) red[tid >> 5] = part;
    __syncthreads();
    if (tid == 0) {
        float v = 0.0f;
#pragma unroll
        for (int w = 0; w < NTHR / 32; w++) v += red[w];
        g_part[slice] = v;
        const unsigned old = atom_inc_acqrel(&g_done);
        s_last = (old == (unsigned)(NWRITER - 1)) ? 1 : 0;
    }
    __syncthreads();

    // ---- last writer: final reduction over all (batch, slice) partials ----
    if (s_last) {
        if (tid < 32) {
            float v = 0.0f;
            if (tid < BB) {
                float sum = 0.0f;
#pragma unroll
                for (int s = 0; s < SLICES; s++) sum += g_part[tid * SLICES + s];
                v = sum * (1.0f / NN) / __ldg(mesh_diameter + labels[tid]);
            }
#pragma unroll
            for (int o = 16; o > 0; o >>= 1) v += __shfl_down_sync(0xffffffffu, v, o);
            if (tid == 0) {
                *out = v * (1.0f / BB);
                g_done = 0;   // reset for next graph replay (deterministic)
            }
        }
    }
}

// ============================================================================
extern "C" void kernel_launch(void* const* d_in, const int* in_sizes, int n_in,
                              void* d_out, int out_size) {
    const float* pred_r        = (const float*)d_in[0];
    const float* gt_r          = (const float*)d_in[1];
    const float* points        = (const float*)d_in[2];
    const float* mesh_diameter = (const float*)d_in[3];
    const int*   labels        = (const int*)d_in[4];
    const void*  sym_flags     = d_in[5];

    fused_kernel<<<dim3(BB, SLICES, PSPLIT), NTHR>>>(
        pred_r, gt_r, points, mesh_diameter, labels, sym_flags, (float*)d_out);
}